// round 2
// baseline (speedup 1.0000x reference)
#include <cuda_runtime.h>
#include <cstdint>

// Problem constants
#define GG   24          // group order
#define OO   16          // output channels
#define II   16          // input channels
#define NCH  384         // O*G == I*G
#define HH   32
#define SPATIAL 32768    // 32^3
#define BATCH 2

// ---------------------------------------------------------------------------
// Device scratch (static __device__ arrays: the sanctioned no-alloc path)
// ---------------------------------------------------------------------------
__device__ float d_Wmat[NCH * NCH];               // 576 KB mix matrix
__device__ float d_Tw[NCH * 27];                  // rotated depthwise taps
__device__ float d_Y[(size_t)BATCH * NCH * SPATIAL]; // 100 MB intermediate

// ---------------------------------------------------------------------------
// Build the 24 proper cube rotations in exactly itertools enumeration order
// ---------------------------------------------------------------------------
__device__ __forceinline__ void build_group(int mats[24][9]) {
    const int perms[6][3] = {{0,1,2},{0,2,1},{1,0,2},{1,2,0},{2,0,1},{2,1,0}};
    int n = 0;
    for (int pi = 0; pi < 6; pi++) {
        for (int si = 0; si < 8; si++) {
            int s0 = (si & 4) ? -1 : 1;
            int s1 = (si & 2) ? -1 : 1;
            int s2 = (si & 1) ? -1 : 1;
            int M[9] = {0,0,0,0,0,0,0,0,0};
            M[0*3 + perms[pi][0]] = s0;
            M[1*3 + perms[pi][1]] = s1;
            M[2*3 + perms[pi][2]] = s2;
            int det = M[0]*(M[4]*M[8]-M[5]*M[7])
                    - M[1]*(M[3]*M[8]-M[5]*M[6])
                    + M[2]*(M[3]*M[7]-M[4]*M[6]);
            if (det == 1) {
                for (int j = 0; j < 9; j++) mats[n][j] = M[j];
                n++;
            }
        }
    }
}

// ---------------------------------------------------------------------------
// Setup: compute SHIFT / ROT_IDX tables, materialize Wmat and Tw
// ---------------------------------------------------------------------------
__global__ void setup_kernel(const float* __restrict__ gw,   // (G,O,I)
                             const float* __restrict__ tw)   // (O,1,3,3,3)
{
    __shared__ int mats[24][9];
    __shared__ int sh[24][24];
    __shared__ int ri[24][27];
    int tid = threadIdx.x;
    if (tid == 0) build_group(mats);
    __syncthreads();

    // SHIFT[g][h] = index of R_g^T R_h
    for (int t = tid; t < 576; t += blockDim.x) {
        int g = t / 24, h = t % 24;
        int P[9];
        #pragma unroll
        for (int a = 0; a < 3; a++)
            #pragma unroll
            for (int b = 0; b < 3; b++) {
                int v = 0;
                #pragma unroll
                for (int k = 0; k < 3; k++) v += mats[g][k*3+a] * mats[h][k*3+b];
                P[a*3+b] = v;
            }
        int idx = 0;
        for (int j = 0; j < 24; j++) {
            bool eq = true;
            #pragma unroll
            for (int q = 0; q < 9; q++) if (mats[j][q] != P[q]) { eq = false; break; }
            if (eq) { idx = j; break; }
        }
        sh[g][h] = idx;
    }

    // ROT_IDX[g][t]: src = (coord - c) @ M_g, then flatten
    for (int t = tid; t < 648; t += blockDim.x) {
        int g = t / 27, tt = t % 27;
        int c0 = tt / 9 - 1, c1 = (tt / 3) % 3 - 1, c2 = tt % 3 - 1;
        int s0 = c0*mats[g][0] + c1*mats[g][3] + c2*mats[g][6] + 1;
        int s1 = c0*mats[g][1] + c1*mats[g][4] + c2*mats[g][7] + 1;
        int s2 = c0*mats[g][2] + c1*mats[g][5] + c2*mats[g][8] + 1;
        ri[g][tt] = s0*9 + s1*3 + s2;
    }
    __syncthreads();

    int gt = blockIdx.x * blockDim.x + tid;
    int stride = gridDim.x * blockDim.x;
    // Wmat[o*24+z][i*24+g] = g_weight[SHIFT[z][g]][o][i]
    for (int idx = gt; idx < NCH * NCH; idx += stride) {
        int co = idx / NCH, ci = idx % NCH;
        int o = co / 24, z = co % 24;
        int i = ci / 24, g = ci % 24;
        d_Wmat[idx] = gw[sh[z][g] * (OO * II) + o * II + i];
    }
    // Tw[o*24+z][t] = t_weight[o][ROT_IDX[z][t]]
    for (int idx = gt; idx < NCH * 27; idx += stride) {
        int c = idx / 27, t = idx % 27;
        int o = c / 24, z = c % 24;
        d_Tw[idx] = tw[o * 27 + ri[z][t]];
    }
}

// ---------------------------------------------------------------------------
// Channel-mix GEMM: Y[b] = Wmat(384x384) * X[b](384x32768), + g_bias[o]
// Tiling: BM=64, BN=64, BK=16, 256 threads, 4x4 microtile
// ---------------------------------------------------------------------------
#define BM 64
#define BN 64
#define BK 16

__global__ __launch_bounds__(256) void gemm_kernel(const float* __restrict__ X,
                                                   const float* __restrict__ gbias)
{
    __shared__ float Ws[BK][BM];   // transposed: Ws[k][co]
    __shared__ float Xs[BK][BN];   // Xs[k][p]

    int b      = blockIdx.z;
    int coTile = blockIdx.y * BM;
    int pTile  = blockIdx.x * BN;

    const float* Xb = X + (size_t)b * NCH * SPATIAL;
    float*       Yb = d_Y + (size_t)b * NCH * SPATIAL;

    int tid = threadIdx.x;
    int tx = tid & 15;         // 0..15  -> p microtile
    int ty = tid >> 4;         // 0..15  -> co microtile

    // load-index precompute
    int wRow = tid >> 2;             // 0..63 : co_local
    int wK4  = (tid & 3) * 4;        // k offset within tile (float4)
    int xRow = tid >> 4;             // 0..15 : k_local
    int xCol = (tid & 15) * 4;       // p offset (float4)

    float acc[4][4] = {};

    for (int k0 = 0; k0 < NCH; k0 += BK) {
        float4 wv = *(const float4*)&d_Wmat[(size_t)(coTile + wRow) * NCH + k0 + wK4];
        Ws[wK4 + 0][wRow] = wv.x;
        Ws[wK4 + 1][wRow] = wv.y;
        Ws[wK4 + 2][wRow] = wv.z;
        Ws[wK4 + 3][wRow] = wv.w;
        *(float4*)&Xs[xRow][xCol] =
            *(const float4*)&Xb[(size_t)(k0 + xRow) * SPATIAL + pTile + xCol];
        __syncthreads();

        #pragma unroll
        for (int kk = 0; kk < BK; kk++) {
            float a[4], bb[4];
            float4 av = *(const float4*)&Ws[kk][ty * 4];
            a[0] = av.x; a[1] = av.y; a[2] = av.z; a[3] = av.w;
            float4 bv = *(const float4*)&Xs[kk][tx * 4];
            bb[0] = bv.x; bb[1] = bv.y; bb[2] = bv.z; bb[3] = bv.w;
            #pragma unroll
            for (int m = 0; m < 4; m++)
                #pragma unroll
                for (int n = 0; n < 4; n++)
                    acc[m][n] = fmaf(a[m], bb[n], acc[m][n]);
        }
        __syncthreads();
    }

    #pragma unroll
    for (int m = 0; m < 4; m++) {
        int co = coTile + ty * 4 + m;
        float gb = __ldg(&gbias[co / 24]);   // g_bias added pre-conv
        float4 v = make_float4(acc[m][0] + gb, acc[m][1] + gb,
                               acc[m][2] + gb, acc[m][3] + gb);
        *(float4*)&Yb[(size_t)co * SPATIAL + pTile + tx * 4] = v;
    }
}

// ---------------------------------------------------------------------------
// Depthwise 3x3x3 conv (pad 1) + t_bias + leaky_relu(0.01)
// One block per (b*384+co, tile of 8h x 8w x 32d); register sliding window
// ---------------------------------------------------------------------------
__global__ __launch_bounds__(256) void conv_kernel(const float* __restrict__ tbias_p,
                                                   float* __restrict__ out)
{
    __shared__ float s[10][10][34];
    __shared__ float twt[27];

    int tid = threadIdx.y * 32 + threadIdx.x;
    int bc  = blockIdx.y;               // b*384 + co
    int h0  = (blockIdx.x >> 2) * 8;
    int w0  = (blockIdx.x & 3) * 8;

    const float* Yc = d_Y + (size_t)bc * SPATIAL;
    if (tid < 27) twt[tid] = d_Tw[(bc % NCH) * 27 + tid];

    // halo tile load: [h0-1,h0+9) x [w0-1,w0+9) x [-1,33)
    for (int idx = tid; idx < 10 * 10 * 34; idx += 256) {
        int hh  = idx / 340;
        int rem = idx % 340;
        int ww  = rem / 34;
        int dd  = rem % 34;
        int gh = h0 + hh - 1, gw = w0 + ww - 1, gd = dd - 1;
        float v = 0.f;
        if ((unsigned)gh < 32u && (unsigned)gw < 32u && (unsigned)gd < 32u)
            v = Yc[((size_t)gh * 32 + gw) * 32 + gd];
        s[hh][ww][dd] = v;
    }
    __syncthreads();

    float tb = __ldg(tbias_p);
    int d  = threadIdx.x;   // 0..31
    int wl = threadIdx.y;   // 0..7

    float v[3][3][3];
    #pragma unroll
    for (int kw = 0; kw < 3; kw++)
        #pragma unroll
        for (int kd = 0; kd < 3; kd++) {
            v[1][kw][kd] = s[0][wl + kw][d + kd];
            v[2][kw][kd] = s[1][wl + kw][d + kd];
        }

    float* Oc = out + (size_t)bc * SPATIAL;
    #pragma unroll
    for (int hl = 0; hl < 8; hl++) {
        #pragma unroll
        for (int kw = 0; kw < 3; kw++)
            #pragma unroll
            for (int kd = 0; kd < 3; kd++) {
                v[0][kw][kd] = v[1][kw][kd];
                v[1][kw][kd] = v[2][kw][kd];
                v[2][kw][kd] = s[hl + 2][wl + kw][d + kd];
            }
        float acc = tb;
        #pragma unroll
        for (int kh = 0; kh < 3; kh++)
            #pragma unroll
            for (int kw = 0; kw < 3; kw++)
                #pragma unroll
                for (int kd = 0; kd < 3; kd++)
                    acc = fmaf(v[kh][kw][kd], twt[(kh * 3 + kw) * 3 + kd], acc);
        float r = acc >= 0.f ? acc : 0.01f * acc;
        Oc[((size_t)(h0 + hl) * 32 + (w0 + wl)) * 32 + d] = r;
    }
}

// ---------------------------------------------------------------------------
// Launch
// ---------------------------------------------------------------------------
extern "C" void kernel_launch(void* const* d_in, const int* in_sizes, int n_in,
                              void* d_out, int out_size)
{
    const float* x  = (const float*)d_in[0];   // (B,I,G,H,H,H)
    const float* gw = (const float*)d_in[1];   // (G,O,I)
    const float* tw = (const float*)d_in[2];   // (O,1,3,3,3)
    const float* gb = (const float*)d_in[3];   // (1,O,1,1,1,1)
    const float* tb = (const float*)d_in[4];   // (1,)
    float* out = (float*)d_out;

    setup_kernel<<<24, 256>>>(gw, tw);
    gemm_kernel<<<dim3(SPATIAL / BN, NCH / BM, BATCH), 256>>>(x, gb);
    conv_kernel<<<dim3(16, BATCH * NCH), dim3(32, 8, 1)>>>(tb, out);
}

// round 5
// speedup vs baseline: 1.7684x; 1.7684x over previous
#include <cuda_runtime.h>
#include <cuda_bf16.h>
#include <cstdint>

// Problem constants
#define GG   24
#define OO   16
#define II   16
#define NCH  384         // O*G == I*G
#define SPATIAL 32768    // 32^3
#define BATCH 2

// ---------------------------------------------------------------------------
// Device scratch
// ---------------------------------------------------------------------------
__device__ __nv_bfloat16 d_Whi[NCH * NCH];
__device__ __nv_bfloat16 d_Wlo[NCH * NCH];
__device__ __nv_bfloat16 d_Xhi[(size_t)BATCH * SPATIAL * NCH];  // [b][p][k]
__device__ __nv_bfloat16 d_Xlo[(size_t)BATCH * SPATIAL * NCH];
__device__ float d_Tw[NCH * 27];
__device__ float d_Y[(size_t)BATCH * NCH * SPATIAL];

__device__ __forceinline__ uint32_t smem_u32(const void* p) {
    uint32_t a;
    asm("{ .reg .u64 t; cvta.to.shared.u64 t, %1; cvt.u32.u64 %0, t; }"
        : "=r"(a) : "l"(p));
    return a;
}
__device__ __forceinline__ void ldsm_x4(uint32_t* r, uint32_t a) {
    asm volatile("ldmatrix.sync.aligned.m8n8.x4.shared.b16 {%0,%1,%2,%3}, [%4];"
                 : "=r"(r[0]), "=r"(r[1]), "=r"(r[2]), "=r"(r[3]) : "r"(a));
}
__device__ __forceinline__ void mma_bf16(float* c, const uint32_t* a, const uint32_t* b) {
    asm volatile(
        "mma.sync.aligned.m16n8k16.row.col.f32.bf16.bf16.f32 "
        "{%0,%1,%2,%3}, {%4,%5,%6,%7}, {%8,%9}, {%0,%1,%2,%3};"
        : "+f"(c[0]), "+f"(c[1]), "+f"(c[2]), "+f"(c[3])
        : "r"(a[0]), "r"(a[1]), "r"(a[2]), "r"(a[3]), "r"(b[0]), "r"(b[1]));
}

// ---------------------------------------------------------------------------
// Octahedral group (itertools enumeration order)
// ---------------------------------------------------------------------------
__device__ __forceinline__ void build_group(int mats[24][9]) {
    const int perms[6][3] = {{0,1,2},{0,2,1},{1,0,2},{1,2,0},{2,0,1},{2,1,0}};
    int n = 0;
    for (int pi = 0; pi < 6; pi++)
        for (int si = 0; si < 8; si++) {
            int s0 = (si & 4) ? -1 : 1;
            int s1 = (si & 2) ? -1 : 1;
            int s2 = (si & 1) ? -1 : 1;
            int M[9] = {0,0,0,0,0,0,0,0,0};
            M[0*3 + perms[pi][0]] = s0;
            M[1*3 + perms[pi][1]] = s1;
            M[2*3 + perms[pi][2]] = s2;
            int det = M[0]*(M[4]*M[8]-M[5]*M[7])
                    - M[1]*(M[3]*M[8]-M[5]*M[6])
                    + M[2]*(M[3]*M[7]-M[4]*M[6]);
            if (det == 1) {
                for (int j = 0; j < 9; j++) mats[n][j] = M[j];
                n++;
            }
        }
}

// ---------------------------------------------------------------------------
// Setup: SHIFT / ROT_IDX tables, W -> bf16 hi/lo mix matrix, rotated taps
// ---------------------------------------------------------------------------
__global__ void setup_kernel(const float* __restrict__ gw,   // (G,O,I)
                             const float* __restrict__ tw)   // (O,1,3,3,3)
{
    __shared__ int mats[24][9];
    __shared__ int sh[24][24];
    __shared__ int ri[24][27];
    int tid = threadIdx.x;
    if (tid == 0) build_group(mats);
    __syncthreads();

    for (int t = tid; t < 576; t += blockDim.x) {
        int g = t / 24, h = t % 24;
        int P[9];
        #pragma unroll
        for (int a = 0; a < 3; a++)
            #pragma unroll
            for (int b = 0; b < 3; b++) {
                int v = 0;
                #pragma unroll
                for (int k = 0; k < 3; k++) v += mats[g][k*3+a] * mats[h][k*3+b];
                P[a*3+b] = v;
            }
        int idx = 0;
        for (int j = 0; j < 24; j++) {
            bool eq = true;
            #pragma unroll
            for (int q = 0; q < 9; q++) if (mats[j][q] != P[q]) { eq = false; break; }
            if (eq) { idx = j; break; }
        }
        sh[g][h] = idx;
    }
    for (int t = tid; t < 648; t += blockDim.x) {
        int g = t / 27, tt = t % 27;
        int c0 = tt / 9 - 1, c1 = (tt / 3) % 3 - 1, c2 = tt % 3 - 1;
        int s0 = c0*mats[g][0] + c1*mats[g][3] + c2*mats[g][6] + 1;
        int s1 = c0*mats[g][1] + c1*mats[g][4] + c2*mats[g][7] + 1;
        int s2 = c0*mats[g][2] + c1*mats[g][5] + c2*mats[g][8] + 1;
        ri[g][tt] = s0*9 + s1*3 + s2;
    }
    __syncthreads();

    int gt = blockIdx.x * blockDim.x + tid;
    int stride = gridDim.x * blockDim.x;
    for (int idx = gt; idx < NCH * NCH; idx += stride) {
        int co = idx / NCH, ci = idx % NCH;
        int o = co / 24, z = co % 24;
        int i = ci / 24, g = ci % 24;
        float v = gw[sh[z][g] * (OO * II) + o * II + i];
        __nv_bfloat16 hi = __float2bfloat16(v);
        __nv_bfloat16 lo = __float2bfloat16(v - __bfloat162float(hi));
        d_Whi[idx] = hi;
        d_Wlo[idx] = lo;
    }
    for (int idx = gt; idx < NCH * 27; idx += stride) {
        int c = idx / 27, t = idx % 27;
        int o = c / 24, z = c % 24;
        d_Tw[idx] = tw[o * 27 + ri[z][t]];
    }
}

// ---------------------------------------------------------------------------
// X transpose + bf16 hi/lo split: (b, c, p) fp32 -> (b, p, c) bf16 x2
// ---------------------------------------------------------------------------
__global__ __launch_bounds__(256) void xsplit_kernel(const float* __restrict__ X)
{
    __shared__ float tile[32][33];
    int tx = threadIdx.x, ty = threadIdx.y;          // (32, 8)
    int p0 = blockIdx.x * 32;
    int c0 = blockIdx.y * 32;
    int b  = blockIdx.z;

    const float* Xb = X + (size_t)b * NCH * SPATIAL;
    #pragma unroll
    for (int r = 0; r < 4; r++)
        tile[ty + 8*r][tx] = Xb[(size_t)(c0 + ty + 8*r) * SPATIAL + p0 + tx];
    __syncthreads();

    size_t obase = ((size_t)b * SPATIAL) * NCH;
    #pragma unroll
    for (int r = 0; r < 4; r++) {
        int pl = ty + 8*r;
        float v = tile[tx][pl];
        __nv_bfloat16 hi = __float2bfloat16(v);
        __nv_bfloat16 lo = __float2bfloat16(v - __bfloat162float(hi));
        size_t oa = obase + (size_t)(p0 + pl) * NCH + c0 + tx;
        d_Xhi[oa] = hi;
        d_Xlo[oa] = lo;
    }
}

// ---------------------------------------------------------------------------
// mma.sync GEMM: Y[b][co][p] = sum_k W[co][k] X[b][k][p]  (+ g_bias)
// Split-bf16 x3 products. CTA tile 128(co) x 128(p), K chunks of 64.
// 8 warps: 2(m) x 4(n), warp tile 64x32.
// ---------------------------------------------------------------------------
#define KC 64
#define NCHUNK 6
#define ROWB 144                      // 128B data + 16B pad (bank-conflict-free)
#define TILEB (128 * ROWB)            // 18432 B per matrix
#define GEMM_SMEM (4 * TILEB)         // Ahi, Alo, Bhi, Blo

__global__ __launch_bounds__(256, 1) void gemm_kernel(const float* __restrict__ gbias)
{
    extern __shared__ char smem[];
    char* sAhi = smem;
    char* sAlo = smem + TILEB;
    char* sBhi = smem + 2 * TILEB;
    char* sBlo = smem + 3 * TILEB;

    int tid = threadIdx.x;
    int wid = tid >> 5;
    int lane = tid & 31;

    int m0 = blockIdx.x * 128;
    int nt = blockIdx.y;
    int b  = nt >> 8;
    int p0 = (nt & 255) * 128;

    int warp_m = wid >> 2;            // 0..1
    int warp_n = wid & 3;             // 0..3

    // ldmatrix source addresses (element within smem tile)
    uint32_t aAddrBase, bAddrBase;
    {
        int am = warp_m * 64 + (lane & 15);         // + mf*16
        int akh = lane >> 4;
        aAddrBase = smem_u32(sAhi) + am * ROWB + akh * 16;
        int bn = warp_n * 32 + (lane & 7) + ((lane >> 4) << 3); // + nf2*16
        int bkh = (lane >> 3) & 1;
        bAddrBase = smem_u32(sBhi) + bn * ROWB + bkh * 16;
    }

    float acc[4][4][4];
    #pragma unroll
    for (int i = 0; i < 4; i++)
        #pragma unroll
        for (int j = 0; j < 4; j++)
            #pragma unroll
            for (int q = 0; q < 4; q++) acc[i][j][q] = 0.f;

    for (int c = 0; c < NCHUNK; c++) {
        int k0 = c * KC;
        __syncthreads();
        // cooperative loads: 4 matrices x 128 rows x 8 segs of 16B
        {
            const char* gA0 = (const char*)(d_Whi + (size_t)m0 * NCH + k0);
            const char* gA1 = (const char*)(d_Wlo + (size_t)m0 * NCH + k0);
            const char* gB0 = (const char*)(d_Xhi + ((size_t)(b * SPATIAL + p0)) * NCH + k0);
            const char* gB1 = (const char*)(d_Xlo + ((size_t)(b * SPATIAL + p0)) * NCH + k0);
            #pragma unroll
            for (int it = 0; it < 16; it++) {
                int t = tid + it * 256;           // 0..4095
                int mat = t >> 10;
                int row = (t >> 3) & 127;
                int seg = t & 7;
                const char* g = (mat == 0 ? gA0 : mat == 1 ? gA1 :
                                 mat == 2 ? gB0 : gB1);
                char* s = (mat == 0 ? sAhi : mat == 1 ? sAlo :
                           mat == 2 ? sBhi : sBlo);
                uint4 v = *(const uint4*)(g + (size_t)row * (NCH * 2) + seg * 16);
                *(uint4*)(s + row * ROWB + seg * 16) = v;
            }
        }
        __syncthreads();

        #pragma unroll
        for (int ks = 0; ks < KC / 16; ks++) {
            uint32_t koff = ks * 32;
            uint32_t ah[4][4], al[4][4], bh[2][4], bl[2][4];
            #pragma unroll
            for (int mf = 0; mf < 4; mf++) {
                ldsm_x4(ah[mf], aAddrBase + mf * (16 * ROWB) + koff);
                ldsm_x4(al[mf], aAddrBase + TILEB + mf * (16 * ROWB) + koff);
            }
            #pragma unroll
            for (int nf2 = 0; nf2 < 2; nf2++) {
                ldsm_x4(bh[nf2], bAddrBase + nf2 * (16 * ROWB) + koff);
                ldsm_x4(bl[nf2], bAddrBase + TILEB + nf2 * (16 * ROWB) + koff);
            }
            #pragma unroll
            for (int mf = 0; mf < 4; mf++)
                #pragma unroll
                for (int nf = 0; nf < 4; nf++) {
                    const uint32_t* bhp = &bh[nf >> 1][(nf & 1) * 2];
                    const uint32_t* blp = &bl[nf >> 1][(nf & 1) * 2];
                    mma_bf16(acc[mf][nf], ah[mf], bhp);
                    mma_bf16(acc[mf][nf], ah[mf], blp);
                    mma_bf16(acc[mf][nf], al[mf], bhp);
                }
        }
    }

    // Epilogue: + g_bias, store to d_Y (row co, p contiguous)
    int tg  = lane >> 2;              // 0..7
    int tir = lane & 3;               // 0..3
    #pragma unroll
    for (int mf = 0; mf < 4; mf++) {
        int r0 = m0 + warp_m * 64 + mf * 16 + tg;
        float bias0 = __ldg(&gbias[r0 / 24]);
        float bias1 = __ldg(&gbias[(r0 + 8) / 24]);
        #pragma unroll
        for (int nf = 0; nf < 4; nf++) {
            int p = p0 + warp_n * 32 + nf * 8 + tir * 2;
            size_t i0 = ((size_t)b * NCH + r0) * SPATIAL + p;
            *(float2*)&d_Y[i0] =
                make_float2(acc[mf][nf][0] + bias0, acc[mf][nf][1] + bias0);
            *(float2*)&d_Y[i0 + 8 * SPATIAL] =
                make_float2(acc[mf][nf][2] + bias1, acc[mf][nf][3] + bias1);
        }
    }
}

// ---------------------------------------------------------------------------
// Depthwise 3x3x3 conv (pad 1) + t_bias + leaky_relu(0.01)
// ---------------------------------------------------------------------------
__global__ __launch_bounds__(256) void conv_kernel(const float* __restrict__ tbias_p,
                                                   float* __restrict__ out)
{
    __shared__ float s[10][10][34];
    __shared__ float twt[27];

    int tid = threadIdx.y * 32 + threadIdx.x;
    int bc  = blockIdx.y;               // b*384 + co
    int h0  = (blockIdx.x >> 2) * 8;
    int w0  = (blockIdx.x & 3) * 8;

    const float* Yc = d_Y + (size_t)bc * SPATIAL;
    if (tid < 27) twt[tid] = d_Tw[(bc % NCH) * 27 + tid];

    for (int idx = tid; idx < 10 * 10 * 34; idx += 256) {
        int hh  = idx / 340;
        int rem = idx % 340;
        int ww  = rem / 34;
        int dd  = rem % 34;
        int gh = h0 + hh - 1, gw = w0 + ww - 1, gd = dd - 1;
        float v = 0.f;
        if ((unsigned)gh < 32u && (unsigned)gw < 32u && (unsigned)gd < 32u)
            v = Yc[((size_t)gh * 32 + gw) * 32 + gd];
        s[hh][ww][dd] = v;
    }
    __syncthreads();

    float tb = __ldg(tbias_p);
    int d  = threadIdx.x;
    int wl = threadIdx.y;

    float v[3][3][3];
    #pragma unroll
    for (int kw = 0; kw < 3; kw++)
        #pragma unroll
        for (int kd = 0; kd < 3; kd++) {
            v[1][kw][kd] = s[0][wl + kw][d + kd];
            v[2][kw][kd] = s[1][wl + kw][d + kd];
        }

    float* Oc = out + (size_t)bc * SPATIAL;
    #pragma unroll
    for (int hl = 0; hl < 8; hl++) {
        #pragma unroll
        for (int kw = 0; kw < 3; kw++)
            #pragma unroll
            for (int kd = 0; kd < 3; kd++) {
                v[0][kw][kd] = v[1][kw][kd];
                v[1][kw][kd] = v[2][kw][kd];
                v[2][kw][kd] = s[hl + 2][wl + kw][d + kd];
            }
        float acc = tb;
        #pragma unroll
        for (int kh = 0; kh < 3; kh++)
            #pragma unroll
            for (int kw = 0; kw < 3; kw++)
                #pragma unroll
                for (int kd = 0; kd < 3; kd++)
                    acc = fmaf(v[kh][kw][kd], twt[(kh * 3 + kw) * 3 + kd], acc);
        float r = acc >= 0.f ? acc : 0.01f * acc;
        Oc[((size_t)(h0 + hl) * 32 + (w0 + wl)) * 32 + d] = r;
    }
}

// ---------------------------------------------------------------------------
// Launch
// ---------------------------------------------------------------------------
extern "C" void kernel_launch(void* const* d_in, const int* in_sizes, int n_in,
                              void* d_out, int out_size)
{
    const float* x  = (const float*)d_in[0];
    const float* gw = (const float*)d_in[1];
    const float* tw = (const float*)d_in[2];
    const float* gb = (const float*)d_in[3];
    const float* tb = (const float*)d_in[4];
    float* out = (float*)d_out;

    cudaFuncSetAttribute(gemm_kernel,
                         cudaFuncAttributeMaxDynamicSharedMemorySize, GEMM_SMEM);

    setup_kernel<<<96, 256>>>(gw, tw);
    xsplit_kernel<<<dim3(SPATIAL / 32, NCH / 32, BATCH), dim3(32, 8)>>>(x);
    gemm_kernel<<<dim3(3, 512), 256, GEMM_SMEM>>>(gb);
    conv_kernel<<<dim3(16, BATCH * NCH), dim3(32, 8, 1)>>>(tb, out);
}